// round 1
// baseline (speedup 1.0000x reference)
#include <cuda_runtime.h>

// ---------------- problem constants ----------------
#define GD 32
#define GH 512
#define GW 512
#define GRID_VOX (GD * GH * GW)     // 8,388,608 voxels
#define NMAX 151552                 // >= 150000, padded
#define MAXP 24576                  // pairs per non-center offset (expect ~2700)
#define CH 128                      // channels (layer1 out / layer2 in & out)

// ---------------- static device scratch (no allocations allowed) ----------------
__device__ int   g_grid[GRID_VOX];          // 32 MB  voxel -> active index (-1 empty)
__device__ float g_h[NMAX * CH];            // 77 MB  layer-1 output
__device__ int   g_cnt[27];                 // rulebook counts
__device__ int   g_pin[27 * MAXP];          // pair input row  (neighbor index)
__device__ int   g_pout[27 * MAXP];         // pair output row (point index)

// ---------------- 1) init grid to -1, counts to 0 ----------------
__global__ void k_init() {
    int i = blockIdx.x * blockDim.x + threadIdx.x;   // one int4 each
    if (i < GRID_VOX / 4) {
        ((int4*)g_grid)[i] = make_int4(-1, -1, -1, -1);
    }
    if (blockIdx.x == 0 && threadIdx.x < 27) g_cnt[threadIdx.x] = 0;
}

// ---------------- 2) scatter active indices into grid ----------------
__global__ void k_scatter(const int* __restrict__ coors, int n) {
    int i = blockIdx.x * blockDim.x + threadIdx.x;
    if (i >= n) return;
    int4 c = ((const int4*)coors)[i];        // (batch, z, y, x)
    g_grid[(c.y * GH + c.z) * GW + c.w] = i;
}

// ---------------- 3) build rulebook: (k != 13) valid neighbor pairs ----------------
__global__ void k_build(const int* __restrict__ coors, int n) {
    int gt = blockIdx.x * blockDim.x + threadIdx.x;
    if (gt >= 27 * n) return;
    int nn = gt % n;            // consecutive threads -> consecutive points (coalesced)
    int k  = gt / n;
    if (k == 13) return;        // center handled densely (neighbor == self always)
    int4 c = ((const int4*)coors)[nn];
    int dz = k / 9 - 1, dy = (k / 3) % 3 - 1, dx = k % 3 - 1;
    int z = c.y + dz, y = c.z + dy, x = c.w + dx;
    if ((unsigned)z >= GD || (unsigned)y >= GH || (unsigned)x >= GW) return;
    int m = g_grid[(z * GH + y) * GW + x];
    if (m < 0) return;
    int slot = atomicAdd(&g_cnt[k], 1);
    if (slot < MAXP) {
        g_pin [k * MAXP + slot] = m;
        g_pout[k * MAXP + slot] = nn;
    }
}

// ---------------- 4a) layer1 center: h[n] = feat[n] @ w1[13]  (Cin=3) ----------------
__global__ void k_l1_center(const float* __restrict__ feat,
                            const float* __restrict__ w1, int n) {
    int gt = blockIdx.x * blockDim.x + threadIdx.x;
    int nn = gt >> 7;
    int c  = gt & 127;
    if (nn >= n) return;
    const float* w = w1 + 13 * 3 * CH;       // w1[13]
    float f0 = feat[nn * 3 + 0];
    float f1 = feat[nn * 3 + 1];
    float f2 = feat[nn * 3 + 2];
    g_h[nn * CH + c] = f0 * w[c] + f1 * w[CH + c] + f2 * w[2 * CH + c];
}

// ---------------- 4b) layer1 pairs: h[out] += feat[in] @ w1[k] ----------------
__global__ void k_l1_pair(const float* __restrict__ feat,
                          const float* __restrict__ w1) {
    int kk = blockIdx.y;
    int k  = kk + (kk >= 13);                // skip center
    int cnt = g_cnt[k]; if (cnt > MAXP) cnt = MAXP;
    int t  = threadIdx.x;
    int pl = t >> 7;                         // 2 pairs per 256-thread block
    int c  = t & 127;
    const float* w = w1 + k * 3 * CH;
    float w0 = w[c], wa = w[CH + c], wb = w[2 * CH + c];   // hoisted per-thread
    for (int pair = blockIdx.x * 2 + pl; pair < cnt; pair += gridDim.x * 2) {
        int m = g_pin [k * MAXP + pair];
        int o = g_pout[k * MAXP + pair];
        float f0 = feat[m * 3 + 0];
        float f1 = feat[m * 3 + 1];
        float f2 = feat[m * 3 + 2];
        atomicAdd(&g_h[o * CH + c], f0 * w0 + f1 * wa + f2 * wb);
    }
}

// ---------------- 5) layer2 center GEMM: out = h @ w2[13]  (store) ----------------
// 128x128 tile per block, 256 threads, 8x8 micro-tile, K chunked by 16.
__global__ __launch_bounds__(256) void k_center_gemm(const float* __restrict__ w2,
                                                     float* __restrict__ out, int n) {
    __shared__ __align__(16) float As[16][132];   // [kk][row], padded
    __shared__ __align__(16) float Bs[16][128];   // [kk][col]
    const float* B = w2 + 13 * CH * CH;
    int t  = threadIdx.x;
    int tx = t & 15, ty = t >> 4;
    int base = blockIdx.x * 128;
    float acc[8][8];
#pragma unroll
    for (int i = 0; i < 8; i++)
#pragma unroll
        for (int j = 0; j < 8; j++) acc[i][j] = 0.f;

#pragma unroll 1
    for (int kt = 0; kt < 8; kt++) {
        __syncthreads();
        // stage A chunk (128 rows x 16 K), transposed into As[kk][row]
#pragma unroll
        for (int q = 0; q < 2; q++) {
            int f = t + q * 256;
            int row = f >> 2, off = f & 3;
            int gr = base + row;
            float4 v = make_float4(0.f, 0.f, 0.f, 0.f);
            if (gr < n) v = *(const float4*)(g_h + (gr * CH + kt * 16 + off * 4));
            As[off * 4 + 0][row] = v.x;
            As[off * 4 + 1][row] = v.y;
            As[off * 4 + 2][row] = v.z;
            As[off * 4 + 3][row] = v.w;
        }
        // stage B chunk (16 K x 128 cols)
#pragma unroll
        for (int q = 0; q < 2; q++) {
            int f = t + q * 256;
            int row = f >> 5, col = (f & 31) * 4;
            *(float4*)&Bs[row][col] = *(const float4*)(B + (kt * 16 + row) * CH + col);
        }
        __syncthreads();
#pragma unroll
        for (int ii = 0; ii < 16; ii++) {
            float4 a0 = *(const float4*)&As[ii][ty * 8];
            float4 a1 = *(const float4*)&As[ii][ty * 8 + 4];
            float4 b0 = *(const float4*)&Bs[ii][tx * 8];
            float4 b1 = *(const float4*)&Bs[ii][tx * 8 + 4];
            float a[8] = {a0.x, a0.y, a0.z, a0.w, a1.x, a1.y, a1.z, a1.w};
            float b[8] = {b0.x, b0.y, b0.z, b0.w, b1.x, b1.y, b1.z, b1.w};
#pragma unroll
            for (int i = 0; i < 8; i++)
#pragma unroll
                for (int j = 0; j < 8; j++) acc[i][j] += a[i] * b[j];
        }
    }
#pragma unroll
    for (int i = 0; i < 8; i++) {
        int r = base + ty * 8 + i;
        if (r < n) {
            *(float4*)(out + r * CH + tx * 8)     = make_float4(acc[i][0], acc[i][1], acc[i][2], acc[i][3]);
            *(float4*)(out + r * CH + tx * 8 + 4) = make_float4(acc[i][4], acc[i][5], acc[i][6], acc[i][7]);
        }
    }
}

// ---------------- 6) layer2 pair GEMM: out[pout] += h[pin] @ w2[k]  (atomic) ----------------
// 64-pair x 128-col tile, 256 threads, 4x8 micro-tile. Grid-stride over tiles per offset.
__global__ __launch_bounds__(256) void k_pair_gemm(const float* __restrict__ w2,
                                                   float* __restrict__ out) {
    __shared__ __align__(16) float As[16][68];
    __shared__ __align__(16) float Bs[16][128];
    __shared__ int s_pin[64], s_pout[64];
    int kk = blockIdx.y;
    int k  = kk + (kk >= 13);
    int cnt = g_cnt[k]; if (cnt > MAXP) cnt = MAXP;
    int t  = threadIdx.x;
    int tx = t & 15, ty = t >> 4;
    const float* B = w2 + k * CH * CH;

    for (int tile = blockIdx.x; tile * 64 < cnt; tile += gridDim.x) {
        int base = tile * 64;
        int rem = cnt - base; if (rem > 64) rem = 64;
        __syncthreads();
        if (t < 64) {
            s_pin [t] = (t < rem) ? g_pin [k * MAXP + base + t] : -1;
            s_pout[t] = (t < rem) ? g_pout[k * MAXP + base + t] : -1;
        }
        __syncthreads();
        float acc[4][8];
#pragma unroll
        for (int i = 0; i < 4; i++)
#pragma unroll
            for (int j = 0; j < 8; j++) acc[i][j] = 0.f;

#pragma unroll 1
        for (int kt = 0; kt < 8; kt++) {
            __syncthreads();
            {   // gather A chunk: 64 rows x 16 K, one float4 per thread
                int row = t >> 2, off = t & 3;
                int m = s_pin[row];
                float4 v = make_float4(0.f, 0.f, 0.f, 0.f);
                if (m >= 0) v = *(const float4*)(g_h + (m * CH + kt * 16 + off * 4));
                As[off * 4 + 0][row] = v.x;
                As[off * 4 + 1][row] = v.y;
                As[off * 4 + 2][row] = v.z;
                As[off * 4 + 3][row] = v.w;
            }
#pragma unroll
            for (int q = 0; q < 2; q++) {
                int f = t + q * 256;
                int row = f >> 5, col = (f & 31) * 4;
                *(float4*)&Bs[row][col] = *(const float4*)(B + (kt * 16 + row) * CH + col);
            }
            __syncthreads();
#pragma unroll
            for (int ii = 0; ii < 16; ii++) {
                float4 av = *(const float4*)&As[ii][ty * 4];
                float4 b0 = *(const float4*)&Bs[ii][tx * 8];
                float4 b1 = *(const float4*)&Bs[ii][tx * 8 + 4];
                float a[4] = {av.x, av.y, av.z, av.w};
                float b[8] = {b0.x, b0.y, b0.z, b0.w, b1.x, b1.y, b1.z, b1.w};
#pragma unroll
                for (int i = 0; i < 4; i++)
#pragma unroll
                    for (int j = 0; j < 8; j++) acc[i][j] += a[i] * b[j];
            }
        }
        // scatter-accumulate
#pragma unroll
        for (int i = 0; i < 4; i++) {
            int po = s_pout[ty * 4 + i];
            if (po >= 0) {
                float* o = out + po * CH + tx * 8;
#pragma unroll
                for (int j = 0; j < 8; j++) atomicAdd(o + j, acc[i][j]);
            }
        }
    }
}

// ---------------- launch ----------------
extern "C" void kernel_launch(void* const* d_in, const int* in_sizes, int n_in,
                              void* d_out, int out_size) {
    const float* feat  = (const float*)d_in[0];   // [N,3]
    const int*   coors = (const int*)  d_in[1];   // [N,4]
    const float* w1    = (const float*)d_in[2];   // [27,3,128]
    const float* w2    = (const float*)d_in[3];   // [27,128,128]
    float* out = (float*)d_out;                   // [N,128]
    int n = in_sizes[0] / 3;

    // 1) grid init
    k_init<<<GRID_VOX / 4 / 256, 256>>>();
    // 2) scatter
    k_scatter<<<(n + 255) / 256, 256>>>(coors, n);
    // 3) rulebook
    k_build<<<(27 * n + 255) / 256, 256>>>(coors, n);
    // 4) layer 1
    k_l1_center<<<(n * CH + 255) / 256, 256>>>(feat, w1, n);
    {
        dim3 g(64, 26);
        k_l1_pair<<<g, 256>>>(feat, w1);
    }
    // 5) layer 2 center GEMM
    k_center_gemm<<<(n + 127) / 128, 256>>>(w2, out, n);
    // 6) layer 2 pair GEMM
    {
        dim3 g(48, 26);
        k_pair_gemm<<<g, 256>>>(w2, out);
    }
}

// round 3
// speedup vs baseline: 1.9622x; 1.9622x over previous
#include <cuda_runtime.h>

// ---------------- problem constants ----------------
#define GD 32
#define GH 512
#define GW 512
#define GRID_VOX (GD * GH * GW)     // 8,388,608 voxels
#define NMAX 151552                 // >= 150000
#define MAXP 8192                   // pairs per non-center offset (expect ~2700)
#define CH 128

// ---------------- static device scratch ----------------
__device__ int   g_grid[GRID_VOX];          // voxel -> active index (-1 empty)
__device__ float g_h[NMAX * CH];            // layer-1 output
__device__ int   g_cnt[27];                 // rulebook counts per offset
__device__ int   g_pin[27 * MAXP];          // pair input row  (neighbor index)
__device__ int   g_pout[27 * MAXP];         // pair output row (point index)
__device__ int   g_in_cnt[NMAX];            // per-point non-center input count
__device__ int   g_in[NMAX * 26];           // packed (k<<18)|m input lists

// ---------------- helpers ----------------
__device__ __forceinline__ unsigned f2tf(float x) {
    unsigned u;
    asm("cvt.rna.tf32.f32 %0, %1;" : "=r"(u) : "f"(x));
    return u;
}
__device__ __forceinline__ float tf(float x) { return __uint_as_float(f2tf(x)); }

__device__ __forceinline__ void mma_tf32(float* d, const unsigned* a, const unsigned* b) {
    asm volatile(
        "mma.sync.aligned.m16n8k8.row.col.f32.tf32.tf32.f32 "
        "{%0,%1,%2,%3},{%4,%5,%6,%7},{%8,%9},{%0,%1,%2,%3};"
        : "+f"(d[0]), "+f"(d[1]), "+f"(d[2]), "+f"(d[3])
        : "r"(a[0]), "r"(a[1]), "r"(a[2]), "r"(a[3]), "r"(b[0]), "r"(b[1]));
}

// ---------------- 1) init ----------------
__global__ void k_init() {
    int i = blockIdx.x * blockDim.x + threadIdx.x;
    if (i < GRID_VOX / 4) ((int4*)g_grid)[i] = make_int4(-1, -1, -1, -1);
    if (i < NMAX) g_in_cnt[i] = 0;
    if (i < 27) g_cnt[i] = 0;
}

// ---------------- 2) scatter active indices ----------------
__global__ void k_scatter(const int* __restrict__ coors, int n) {
    int i = blockIdx.x * blockDim.x + threadIdx.x;
    if (i >= n) return;
    int4 c = ((const int4*)coors)[i];        // (batch, z, y, x)
    g_grid[(c.y * GH + c.z) * GW + c.w] = i;
}

// ---------------- 3) rulebook: offset-grouped pairs + per-point input lists ----------------
__global__ void k_build(const int* __restrict__ coors, int n) {
    int gt = blockIdx.x * blockDim.x + threadIdx.x;
    if (gt >= 27 * n) return;
    int nn = gt % n;
    int k  = gt / n;
    if (k == 13) return;                     // center handled densely
    int4 c = ((const int4*)coors)[nn];
    int dz = k / 9 - 1, dy = (k / 3) % 3 - 1, dx = k % 3 - 1;
    int z = c.y + dz, y = c.z + dy, x = c.w + dx;
    if ((unsigned)z >= GD || (unsigned)y >= GH || (unsigned)x >= GW) return;
    int m = g_grid[(z * GH + y) * GW + x];
    if (m < 0) return;
    int slot = atomicAdd(&g_cnt[k], 1);
    if (slot < MAXP) {
        g_pin [k * MAXP + slot] = m;
        g_pout[k * MAXP + slot] = nn;
    }
    int s = atomicAdd(&g_in_cnt[nn], 1);     // <= 26, always fits
    g_in[nn * 26 + s] = (k << 18) | m;
}

// ---------------- 4) layer1 fused gather: h[i] = sum_k feat[nbr] @ w1[k] ----------------
// one warp per point; thread handles 4 channels (float4); no atomics.
__global__ void k_l1_fused(const float* __restrict__ feat,
                           const float* __restrict__ w1, int n) {
    int gt = blockIdx.x * blockDim.x + threadIdx.x;
    int nn = gt >> 5;
    if (nn >= n) return;
    int c = (gt & 31) * 4;

    // center contribution
    float f0 = feat[nn * 3 + 0];
    float f1 = feat[nn * 3 + 1];
    float f2 = feat[nn * 3 + 2];
    const float* wc = w1 + 13 * 3 * CH;
    float4 r0 = *(const float4*)(wc + c);
    float4 r1 = *(const float4*)(wc + CH + c);
    float4 r2 = *(const float4*)(wc + 2 * CH + c);
    float4 acc;
    acc.x = f0 * r0.x + f1 * r1.x + f2 * r2.x;
    acc.y = f0 * r0.y + f1 * r1.y + f2 * r2.y;
    acc.z = f0 * r0.z + f1 * r1.z + f2 * r2.z;
    acc.w = f0 * r0.w + f1 * r1.w + f2 * r2.w;

    int cnt = g_in_cnt[nn];
    for (int s = 0; s < cnt; s++) {
        int packed = g_in[nn * 26 + s];
        int k = packed >> 18;
        int m = packed & 0x3FFFF;
        float g0 = feat[m * 3 + 0];
        float g1 = feat[m * 3 + 1];
        float g2 = feat[m * 3 + 2];
        const float* w = w1 + k * 3 * CH;
        float4 q0 = *(const float4*)(w + c);
        float4 q1 = *(const float4*)(w + CH + c);
        float4 q2 = *(const float4*)(w + 2 * CH + c);
        acc.x += g0 * q0.x + g1 * q1.x + g2 * q2.x;
        acc.y += g0 * q0.y + g1 * q1.y + g2 * q2.y;
        acc.z += g0 * q0.z + g1 * q1.z + g2 * q2.z;
        acc.w += g0 * q0.w + g1 * q1.w + g2 * q2.w;
    }
    *(float4*)(g_h + nn * CH + c) = acc;
}

// ---------------- 5) layer2 center GEMM (tf32 mma): out = h @ w2[13] ----------------
// 128x128 tile, 256 threads = 8 warps (4x2), warp tile 32x64, K chunk 32.
__global__ __launch_bounds__(256) void k_center_mma(const float* __restrict__ w2,
                                                    float* __restrict__ out, int n) {
    __shared__ float As[128][36];
    __shared__ float Bs[32][132];
    const float* B = w2 + 13 * CH * CH;
    int t = threadIdx.x;
    int wid = t >> 5, lane = t & 31;
    int wm = (wid >> 1) * 32, wn = (wid & 1) * 64;
    int lr = lane >> 2, lc = lane & 3;
    int base = blockIdx.x * 128;
    float acc[2][8][4];
#pragma unroll
    for (int i = 0; i < 2; i++)
#pragma unroll
        for (int j = 0; j < 8; j++)
#pragma unroll
            for (int q = 0; q < 4; q++) acc[i][j][q] = 0.f;

#pragma unroll 1
    for (int kt = 0; kt < 4; kt++) {
        __syncthreads();
#pragma unroll
        for (int q = 0; q < 4; q++) {          // A: 128 rows x 32 k
            int idx = t + q * 256;             // 1024 float4 slots
            int row = idx >> 3, c8 = idx & 7;
            int gr = base + row;
            float4 v = make_float4(0.f, 0.f, 0.f, 0.f);
            if (gr < n) v = *(const float4*)(g_h + gr * CH + kt * 32 + c8 * 4);
            As[row][c8 * 4 + 0] = tf(v.x);
            As[row][c8 * 4 + 1] = tf(v.y);
            As[row][c8 * 4 + 2] = tf(v.z);
            As[row][c8 * 4 + 3] = tf(v.w);
        }
#pragma unroll
        for (int q = 0; q < 4; q++) {          // B: 32 k x 128 cols
            int idx = t + q * 256;
            int row = idx >> 5, c4 = idx & 31;
            float4 v = *(const float4*)(B + (kt * 32 + row) * CH + c4 * 4);
            Bs[row][c4 * 4 + 0] = tf(v.x);
            Bs[row][c4 * 4 + 1] = tf(v.y);
            Bs[row][c4 * 4 + 2] = tf(v.z);
            Bs[row][c4 * 4 + 3] = tf(v.w);
        }
        __syncthreads();
#pragma unroll
        for (int k8 = 0; k8 < 4; k8++) {
            unsigned a[2][4];
#pragma unroll
            for (int i = 0; i < 2; i++) {
                int r0 = wm + i * 16 + lr;
                a[i][0] = __float_as_uint(As[r0][k8 * 8 + lc]);
                a[i][1] = __float_as_uint(As[r0 + 8][k8 * 8 + lc]);
                a[i][2] = __float_as_uint(As[r0][k8 * 8 + lc + 4]);
                a[i][3] = __float_as_uint(As[r0 + 8][k8 * 8 + lc + 4]);
            }
#pragma unroll
            for (int j = 0; j < 8; j++) {
                unsigned b[2];
                int col = wn + j * 8 + lr;
                b[0] = __float_as_uint(Bs[k8 * 8 + lc][col]);
                b[1] = __float_as_uint(Bs[k8 * 8 + lc + 4][col]);
                mma_tf32(acc[0][j], a[0], b);
                mma_tf32(acc[1][j], a[1], b);
            }
        }
    }
#pragma unroll
    for (int i = 0; i < 2; i++)
#pragma unroll
        for (int j = 0; j < 8; j++) {
            int r0 = base + wm + i * 16 + lr;
            int c0 = wn + j * 8 + lc * 2;
            if (r0 < n)
                *(float2*)(out + r0 * CH + c0) = make_float2(acc[i][j][0], acc[i][j][1]);
            if (r0 + 8 < n)
                *(float2*)(out + (r0 + 8) * CH + c0) = make_float2(acc[i][j][2], acc[i][j][3]);
        }
}

// ---------------- 6) layer2 pair GEMM (tf32 mma): out[pout] += h[pin] @ w2[k] ----------------
// 128-pair x 128-col tile, same mma core, atomic scatter-accumulate.
__global__ __launch_bounds__(256) void k_pair_mma(const float* __restrict__ w2,
                                                  float* __restrict__ out) {
    __shared__ float As[128][36];
    __shared__ float Bs[32][132];
    __shared__ int s_pin[128], s_pout[128];
    int kk = blockIdx.y;
    int k  = kk + (kk >= 13);
    int cnt = g_cnt[k]; if (cnt > MAXP) cnt = MAXP;
    const float* B = w2 + k * CH * CH;
    int t = threadIdx.x;
    int wid = t >> 5, lane = t & 31;
    int wm = (wid >> 1) * 32, wn = (wid & 1) * 64;
    int lr = lane >> 2, lc = lane & 3;

    for (int tile = blockIdx.x; tile * 128 < cnt; tile += gridDim.x) {
        int base = tile * 128;
        __syncthreads();
        if (t < 128) {
            int ok = (base + t < cnt);
            s_pin [t] = ok ? g_pin [k * MAXP + base + t] : -1;
            s_pout[t] = ok ? g_pout[k * MAXP + base + t] : -1;
        }
        __syncthreads();
        float acc[2][8][4];
#pragma unroll
        for (int i = 0; i < 2; i++)
#pragma unroll
            for (int j = 0; j < 8; j++)
#pragma unroll
                for (int q = 0; q < 4; q++) acc[i][j][q] = 0.f;

#pragma unroll 1
        for (int kt = 0; kt < 4; kt++) {
            __syncthreads();
#pragma unroll
            for (int q = 0; q < 4; q++) {
                int idx = t + q * 256;
                int row = idx >> 3, c8 = idx & 7;
                int m = s_pin[row];
                float4 v = make_float4(0.f, 0.f, 0.f, 0.f);
                if (m >= 0) v = *(const float4*)(g_h + m * CH + kt * 32 + c8 * 4);
                As[row][c8 * 4 + 0] = tf(v.x);
                As[row][c8 * 4 + 1] = tf(v.y);
                As[row][c8 * 4 + 2] = tf(v.z);
                As[row][c8 * 4 + 3] = tf(v.w);
            }
#pragma unroll
            for (int q = 0; q < 4; q++) {
                int idx = t + q * 256;
                int row = idx >> 5, c4 = idx & 31;
                float4 v = *(const float4*)(B + (kt * 32 + row) * CH + c4 * 4);
                Bs[row][c4 * 4 + 0] = tf(v.x);
                Bs[row][c4 * 4 + 1] = tf(v.y);
                Bs[row][c4 * 4 + 2] = tf(v.z);
                Bs[row][c4 * 4 + 3] = tf(v.w);
            }
            __syncthreads();
#pragma unroll
            for (int k8 = 0; k8 < 4; k8++) {
                unsigned a[2][4];
#pragma unroll
                for (int i = 0; i < 2; i++) {
                    int r0 = wm + i * 16 + lr;
                    a[i][0] = __float_as_uint(As[r0][k8 * 8 + lc]);
                    a[i][1] = __float_as_uint(As[r0 + 8][k8 * 8 + lc]);
                    a[i][2] = __float_as_uint(As[r0][k8 * 8 + lc + 4]);
                    a[i][3] = __float_as_uint(As[r0 + 8][k8 * 8 + lc + 4]);
                }
#pragma unroll
                for (int j = 0; j < 8; j++) {
                    unsigned b[2];
                    int col = wn + j * 8 + lr;
                    b[0] = __float_as_uint(Bs[k8 * 8 + lc][col]);
                    b[1] = __float_as_uint(Bs[k8 * 8 + lc + 4][col]);
                    mma_tf32(acc[0][j], a[0], b);
                    mma_tf32(acc[1][j], a[1], b);
                }
            }
        }
        // scatter-accumulate
#pragma unroll
        for (int i = 0; i < 2; i++) {
            int r0 = wm + i * 16 + lr;
            int po0 = s_pout[r0];
            int po1 = s_pout[r0 + 8];
#pragma unroll
            for (int j = 0; j < 8; j++) {
                int c0 = wn + j * 8 + lc * 2;
                if (po0 >= 0) {
                    atomicAdd(out + po0 * CH + c0,     acc[i][j][0]);
                    atomicAdd(out + po0 * CH + c0 + 1, acc[i][j][1]);
                }
                if (po1 >= 0) {
                    atomicAdd(out + po1 * CH + c0,     acc[i][j][2]);
                    atomicAdd(out + po1 * CH + c0 + 1, acc[i][j][3]);
                }
            }
        }
    }
}

// ---------------- launch ----------------
extern "C" void kernel_launch(void* const* d_in, const int* in_sizes, int n_in,
                              void* d_out, int out_size) {
    const float* feat  = (const float*)d_in[0];   // [N,3]
    const int*   coors = (const int*)  d_in[1];   // [N,4]
    const float* w1    = (const float*)d_in[2];   // [27,3,128]
    const float* w2    = (const float*)d_in[3];   // [27,128,128]
    float* out = (float*)d_out;                   // [N,128]
    int n = in_sizes[0] / 3;

    k_init<<<GRID_VOX / 4 / 256, 256>>>();
    k_scatter<<<(n + 255) / 256, 256>>>(coors, n);
    k_build<<<(27 * n + 255) / 256, 256>>>(coors, n);
    k_l1_fused<<<(n * 32 + 255) / 256, 256>>>(feat, w1, n);
    k_center_mma<<<(n + 127) / 128, 256>>>(w2, out, n);
    {
        dim3 g(24, 26);
        k_pair_mma<<<g, 256>>>(w2, out);
    }
}

// round 4
// speedup vs baseline: 2.2376x; 1.1404x over previous
#include <cuda_runtime.h>

// ---------------- problem constants ----------------
#define GD 32
#define GH 512
#define GW 512
#define GRID_VOX (GD * GH * GW)
#define NMAX 151552
#define MAXP 8192
#define CH 128

// ---------------- static device scratch (zero-initialized at load) ----------------
__device__ int   g_grid[GRID_VOX];          // voxel -> active index + 1 (0 = empty)
__device__ float g_h[NMAX * CH];            // layer-1 output (tf32-rounded)
__device__ int   g_cnt[27];                 // rulebook counts per offset
__device__ int   g_pin[27 * MAXP];          // pair input row
__device__ int   g_pout[27 * MAXP];         // pair output row
__device__ int   g_in_cnt[NMAX];            // per-point input count (plain store)
__device__ int   g_in[NMAX * 26];           // packed (k<<18)|m
__device__ float g_w2t[27 * CH * CH];       // tf32-rounded w2

// ---------------- helpers ----------------
__device__ __forceinline__ float tf(float x) {
    unsigned u;
    asm("cvt.rna.tf32.f32 %0, %1;" : "=r"(u) : "f"(x));
    return __uint_as_float(u);
}
__device__ __forceinline__ void mma_tf32(float* d, const unsigned* a, const unsigned* b) {
    asm volatile(
        "mma.sync.aligned.m16n8k8.row.col.f32.tf32.tf32.f32 "
        "{%0,%1,%2,%3},{%4,%5,%6,%7},{%8,%9},{%0,%1,%2,%3};"
        : "+f"(d[0]), "+f"(d[1]), "+f"(d[2]), "+f"(d[3])
        : "r"(a[0]), "r"(a[1]), "r"(a[2]), "r"(a[3]), "r"(b[0]), "r"(b[1]));
}
__device__ __forceinline__ void cp16(void* dst, const void* src, bool pred) {
    unsigned d = (unsigned)__cvta_generic_to_shared(dst);
    int sz = pred ? 16 : 0;
    asm volatile("cp.async.cg.shared.global [%0], [%1], 16, %2;\n"
                 :: "r"(d), "l"(src), "r"(sz));
}
#define CP_COMMIT() asm volatile("cp.async.commit_group;\n")
#define CP_WAIT0()  asm volatile("cp.async.wait_group 0;\n")
#define CP_WAIT1()  asm volatile("cp.async.wait_group 1;\n")
__device__ __forceinline__ void red2(float* addr, float a, float b) {
    asm volatile("red.global.add.v2.f32 [%0], {%1,%2};" :: "l"(addr), "f"(a), "f"(b) : "memory");
}

// ---------------- 1) scatter: grid[vox] = i+1 ----------------
__global__ void k_scatter(const int* __restrict__ coors, int n) {
    int i = blockIdx.x * blockDim.x + threadIdx.x;
    if (i >= n) return;
    int4 c = ((const int4*)coors)[i];        // (batch, z, y, x)
    g_grid[(c.y * GH + c.z) * GW + c.w] = i + 1;
}

// ---------------- 2) rulebook: one thread per point, warp-agg atomics ----------------
__global__ void k_build(const int* __restrict__ coors, int n) {
    int nn = blockIdx.x * blockDim.x + threadIdx.x;
    bool act = (nn < n);
    int4 c = make_int4(0, 0, 0, 0);
    if (act) c = ((const int4*)coors)[nn];
    int lane = threadIdx.x & 31;
    int s = 0;
#pragma unroll
    for (int k = 0; k < 27; k++) {
        if (k == 13) continue;
        const int dz = k / 9 - 1, dy = (k / 3) % 3 - 1, dx = k % 3 - 1;
        int z = c.y + dz, y = c.z + dy, x = c.w + dx;
        int m = -1;
        if (act && (unsigned)z < GD && (unsigned)y < GH && (unsigned)x < GW)
            m = g_grid[(z * GH + y) * GW + x] - 1;
        bool valid = (m >= 0);
        unsigned mask = __ballot_sync(0xffffffffu, valid);
        if (mask) {
            int leader = __ffs(mask) - 1;
            int basec = 0;
            if (lane == leader) basec = atomicAdd(&g_cnt[k], __popc(mask));
            basec = __shfl_sync(0xffffffffu, basec, leader);
            if (valid) {
                int pos = basec + __popc(mask & ((1u << lane) - 1u));
                if (pos < MAXP) {
                    g_pin [k * MAXP + pos] = m;
                    g_pout[k * MAXP + pos] = nn;
                }
                g_in[nn * 26 + s] = (k << 18) | m;
                s++;
            }
        }
    }
    if (act) g_in_cnt[nn] = s;
}

// ---------------- 3) layer1 fused gather (writes tf32-rounded h) ----------------
__global__ void k_l1_fused(const float* __restrict__ feat,
                           const float* __restrict__ w1, int n) {
    int gt = blockIdx.x * blockDim.x + threadIdx.x;
    int nn = gt >> 5;
    if (nn >= n) return;
    int c = (gt & 31) * 4;

    float f0 = feat[nn * 3 + 0];
    float f1 = feat[nn * 3 + 1];
    float f2 = feat[nn * 3 + 2];
    const float* wc = w1 + 13 * 3 * CH;
    float4 r0 = *(const float4*)(wc + c);
    float4 r1 = *(const float4*)(wc + CH + c);
    float4 r2 = *(const float4*)(wc + 2 * CH + c);
    float4 acc;
    acc.x = f0 * r0.x + f1 * r1.x + f2 * r2.x;
    acc.y = f0 * r0.y + f1 * r1.y + f2 * r2.y;
    acc.z = f0 * r0.z + f1 * r1.z + f2 * r2.z;
    acc.w = f0 * r0.w + f1 * r1.w + f2 * r2.w;

    int cnt = g_in_cnt[nn];
    for (int s = 0; s < cnt; s++) {
        int packed = g_in[nn * 26 + s];
        int k = packed >> 18;
        int m = packed & 0x3FFFF;
        float g0 = feat[m * 3 + 0];
        float g1 = feat[m * 3 + 1];
        float g2 = feat[m * 3 + 2];
        const float* w = w1 + k * 3 * CH;
        float4 q0 = *(const float4*)(w + c);
        float4 q1 = *(const float4*)(w + CH + c);
        float4 q2 = *(const float4*)(w + 2 * CH + c);
        acc.x += g0 * q0.x + g1 * q1.x + g2 * q2.x;
        acc.y += g0 * q0.y + g1 * q1.y + g2 * q2.y;
        acc.z += g0 * q0.z + g1 * q1.z + g2 * q2.z;
        acc.w += g0 * q0.w + g1 * q1.w + g2 * q2.w;
    }
    acc.x = tf(acc.x); acc.y = tf(acc.y); acc.z = tf(acc.z); acc.w = tf(acc.w);
    *(float4*)(g_h + nn * CH + c) = acc;
}

// ---------------- 4) pre-round w2 to tf32 ----------------
__global__ void k_cvtw2(const float* __restrict__ w2) {
    int i = blockIdx.x * blockDim.x + threadIdx.x;
    if (i >= 27 * CH * CH / 4) return;
    float4 v = ((const float4*)w2)[i];
    v.x = tf(v.x); v.y = tf(v.y); v.z = tf(v.z); v.w = tf(v.w);
    ((float4*)g_w2t)[i] = v;
}

// ---------------- 5) layer2 center GEMM: cp.async double-buffered, K chunk 16 ----------------
__global__ __launch_bounds__(256) void k_center_mma(float* __restrict__ out, int n) {
    __shared__ float As[2][128][20];
    __shared__ float Bs[2][16][132];
    const float* B = g_w2t + 13 * CH * CH;
    int t = threadIdx.x;
    int wid = t >> 5, lane = t & 31;
    int wm = (wid >> 1) * 32, wn = (wid & 1) * 64;
    int lr = lane >> 2, lc = lane & 3;
    int base = blockIdx.x * 128;
    float acc[2][8][4];
#pragma unroll
    for (int i = 0; i < 2; i++)
#pragma unroll
        for (int j = 0; j < 8; j++)
#pragma unroll
            for (int q = 0; q < 4; q++) acc[i][j][q] = 0.f;

    // staging indices
    int arow = t >> 1, ac4 = (t & 1) * 2;        // A: 2 float4 per thread (rows via 2 steps)
    int brow = t >> 5, bc4 = t & 31;             // B: 512 float4 -> 2 per thread

    auto stage = [&](int s, int kt) {
#pragma unroll
        for (int q = 0; q < 2; q++) {
            int idx = t + q * 256;               // 512 float4 slots for A
            int row = idx >> 2, c4 = idx & 3;
            int gr = base + row;
            cp16(&As[s][row][c4 * 4], g_h + gr * CH + kt * 16 + c4 * 4, gr < n);
        }
#pragma unroll
        for (int q = 0; q < 2; q++) {
            int idx = t + q * 256;               // 512 float4 slots for B
            int row = idx >> 5, c4 = idx & 31;
            cp16(&Bs[s][row][c4 * 4], B + (kt * 16 + row) * CH + c4 * 4, true);
        }
    };
    (void)arow; (void)ac4; (void)brow; (void)bc4;

    stage(0, 0);
    CP_COMMIT();
#pragma unroll 1
    for (int kt = 0; kt < 8; kt++) {
        int s = kt & 1;
        if (kt + 1 < 8) { stage(s ^ 1, kt + 1); CP_COMMIT(); CP_WAIT1(); }
        else           { CP_WAIT0(); }
        __syncthreads();
#pragma unroll
        for (int k8 = 0; k8 < 2; k8++) {
            unsigned a[2][4];
#pragma unroll
            for (int i = 0; i < 2; i++) {
                int r0 = wm + i * 16 + lr;
                a[i][0] = __float_as_uint(As[s][r0][k8 * 8 + lc]);
                a[i][1] = __float_as_uint(As[s][r0 + 8][k8 * 8 + lc]);
                a[i][2] = __float_as_uint(As[s][r0][k8 * 8 + lc + 4]);
                a[i][3] = __float_as_uint(As[s][r0 + 8][k8 * 8 + lc + 4]);
            }
#pragma unroll
            for (int j = 0; j < 8; j++) {
                unsigned b[2];
                int col = wn + j * 8 + lr;
                b[0] = __float_as_uint(Bs[s][k8 * 8 + lc][col]);
                b[1] = __float_as_uint(Bs[s][k8 * 8 + lc + 4][col]);
                mma_tf32(acc[0][j], a[0], b);
                mma_tf32(acc[1][j], a[1], b);
            }
        }
        __syncthreads();
    }
#pragma unroll
    for (int i = 0; i < 2; i++)
#pragma unroll
        for (int j = 0; j < 8; j++) {
            int r0 = base + wm + i * 16 + lr;
            int c0 = wn + j * 8 + lc * 2;
            if (r0 < n)
                *(float2*)(out + r0 * CH + c0) = make_float2(acc[i][j][0], acc[i][j][1]);
            if (r0 + 8 < n)
                *(float2*)(out + (r0 + 8) * CH + c0) = make_float2(acc[i][j][2], acc[i][j][3]);
        }
}

// ---------------- 6) layer2 pair GEMM: same core, red.v2 scatter ----------------
__global__ __launch_bounds__(256) void k_pair_mma(float* __restrict__ out) {
    __shared__ float As[2][128][20];
    __shared__ float Bs[2][16][132];
    __shared__ int s_pin[128], s_pout[128];
    int kk = blockIdx.y;
    int k  = kk + (kk >= 13);
    int cnt = g_cnt[k]; if (cnt > MAXP) cnt = MAXP;
    const float* B = g_w2t + k * CH * CH;
    int t = threadIdx.x;
    int wid = t >> 5, lane = t & 31;
    int wm = (wid >> 1) * 32, wn = (wid & 1) * 64;
    int lr = lane >> 2, lc = lane & 3;

    for (int tile = blockIdx.x; tile * 128 < cnt; tile += gridDim.x) {
        int base = tile * 128;
        __syncthreads();
        if (t < 128) {
            int ok = (base + t < cnt);
            s_pin [t] = ok ? g_pin [k * MAXP + base + t] : -1;
            s_pout[t] = ok ? g_pout[k * MAXP + base + t] : -1;
        }
        __syncthreads();
        float acc[2][8][4];
#pragma unroll
        for (int i = 0; i < 2; i++)
#pragma unroll
            for (int j = 0; j < 8; j++)
#pragma unroll
                for (int q = 0; q < 4; q++) acc[i][j][q] = 0.f;

        auto stage = [&](int s, int kt) {
#pragma unroll
            for (int q = 0; q < 2; q++) {
                int idx = t + q * 256;
                int row = idx >> 2, c4 = idx & 3;
                int m = s_pin[row];
                int mm = m < 0 ? 0 : m;
                cp16(&As[s][row][c4 * 4], g_h + mm * CH + kt * 16 + c4 * 4, m >= 0);
            }
#pragma unroll
            for (int q = 0; q < 2; q++) {
                int idx = t + q * 256;
                int row = idx >> 5, c4 = idx & 31;
                cp16(&Bs[s][row][c4 * 4], B + (kt * 16 + row) * CH + c4 * 4, true);
            }
        };

        stage(0, 0);
        CP_COMMIT();
#pragma unroll 1
        for (int kt = 0; kt < 8; kt++) {
            int s = kt & 1;
            if (kt + 1 < 8) { stage(s ^ 1, kt + 1); CP_COMMIT(); CP_WAIT1(); }
            else           { CP_WAIT0(); }
            __syncthreads();
#pragma unroll
            for (int k8 = 0; k8 < 2; k8++) {
                unsigned a[2][4];
#pragma unroll
                for (int i = 0; i < 2; i++) {
                    int r0 = wm + i * 16 + lr;
                    a[i][0] = __float_as_uint(As[s][r0][k8 * 8 + lc]);
                    a[i][1] = __float_as_uint(As[s][r0 + 8][k8 * 8 + lc]);
                    a[i][2] = __float_as_uint(As[s][r0][k8 * 8 + lc + 4]);
                    a[i][3] = __float_as_uint(As[s][r0 + 8][k8 * 8 + lc + 4]);
                }
#pragma unroll
                for (int j = 0; j < 8; j++) {
                    unsigned b[2];
                    int col = wn + j * 8 + lr;
                    b[0] = __float_as_uint(Bs[s][k8 * 8 + lc][col]);
                    b[1] = __float_as_uint(Bs[s][k8 * 8 + lc + 4][col]);
                    mma_tf32(acc[0][j], a[0], b);
                    mma_tf32(acc[1][j], a[1], b);
                }
            }
            __syncthreads();
        }
        // scatter-accumulate with vector reductions
#pragma unroll
        for (int i = 0; i < 2; i++) {
            int r0 = wm + i * 16 + lr;
            int po0 = s_pout[r0];
            int po1 = s_pout[r0 + 8];
#pragma unroll
            for (int j = 0; j < 8; j++) {
                int c0 = wn + j * 8 + lc * 2;
                if (po0 >= 0) red2(out + po0 * CH + c0, acc[i][j][0], acc[i][j][1]);
                if (po1 >= 0) red2(out + po1 * CH + c0, acc[i][j][2], acc[i][j][3]);
            }
        }
    }
}

// ---------------- 7) cleanup: restore zero-state for next replay ----------------
__global__ void k_cleanup(const int* __restrict__ coors, int n) {
    int i = blockIdx.x * blockDim.x + threadIdx.x;
    if (i < n) {
        int4 c = ((const int4*)coors)[i];
        g_grid[(c.y * GH + c.z) * GW + c.w] = 0;
    }
    if (i < 27) g_cnt[i] = 0;
}

// ---------------- launch ----------------
extern "C" void kernel_launch(void* const* d_in, const int* in_sizes, int n_in,
                              void* d_out, int out_size) {
    const float* feat  = (const float*)d_in[0];   // [N,3]
    const int*   coors = (const int*)  d_in[1];   // [N,4]
    const float* w1    = (const float*)d_in[2];   // [27,3,128]
    const float* w2    = (const float*)d_in[3];   // [27,128,128]
    float* out = (float*)d_out;                   // [N,128]
    int n = in_sizes[0] / 3;

    k_scatter<<<(n + 255) / 256, 256>>>(coors, n);
    k_build<<<(n + 255) / 256, 256>>>(coors, n);
    k_l1_fused<<<(n * 32 + 255) / 256, 256>>>(feat, w1, n);
    k_cvtw2<<<(27 * CH * CH / 4 + 255) / 256, 256>>>(w2);
    k_center_mma<<<(n + 127) / 128, 256>>>(out, n);
    {
        dim3 g(24, 26);
        k_pair_mma<<<g, 256>>>(out);
    }
    k_cleanup<<<(n + 255) / 256, 256>>>(coors, n);
}